// round 2
// baseline (speedup 1.0000x reference)
#include <cuda_runtime.h>

#define TT 2048
#define BB 32
#define HH 256
#define G3 768
#define NS 1024
#define EMBD 63

// ---------- persistent device scratch (no allocations) ----------
__device__ float    d_Eg[2][NS][G3];          // bi + embed @ Wi[1:]
__device__ float    d_H[2][TT + 1][BB][HH];   // hidden history, both dirs
__device__ unsigned d_Cnt[2][4][TT + 1];      // (dir, batch-group, t) arrival counters

// ---------- f32x2 helpers ----------
__device__ __forceinline__ unsigned long long pk2(float a, float b) {
    unsigned long long r;
    asm("mov.b64 %0, {%1, %2};" : "=l"(r) : "f"(a), "f"(b));
    return r;
}
__device__ __forceinline__ void fma2(unsigned long long& d, unsigned long long a,
                                     unsigned long long b) {
    asm("fma.rn.f32x2 %0, %1, %2, %0;" : "+l"(d) : "l"(a), "l"(b));
}
__device__ __forceinline__ float2 up2(unsigned long long v) {
    float lo, hi;
    asm("mov.b64 {%0, %1}, %2;" : "=f"(lo), "=f"(hi) : "l"(v));
    return make_float2(lo, hi);
}

// =====================================================================
// Kernel A: E[dir] = bi + embed @ Wi[1:, :]; zero sync counters.
// grid 128, block 256 (8 singers/CTA; thread owns columns c, 256+c, 512+c)
// =====================================================================
__global__ void __launch_bounds__(256) precompute_kernel(
    const float* __restrict__ embed,
    const float* __restrict__ Wif, const float* __restrict__ bif,
    const float* __restrict__ Wib, const float* __restrict__ bib)
{
    const int tid = threadIdx.x;
    const int gid = blockIdx.x * 256 + tid;
    if (gid < 2 * 4 * (TT + 1)) reinterpret_cast<unsigned*>(d_Cnt)[gid] = 0u;

    __shared__ float emb[8][EMBD];
    const int sb = blockIdx.x * 8;
    for (int i = tid; i < 8 * EMBD; i += 256)
        emb[i / EMBD][i % EMBD] = embed[sb * EMBD + i];
    __syncthreads();

    const int c = tid;
    float af0[8], af1[8], af2[8], ab0[8], ab1[8], ab2[8];
#pragma unroll
    for (int s = 0; s < 8; s++) { af0[s]=af1[s]=af2[s]=ab0[s]=ab1[s]=ab2[s]=0.f; }

    for (int e = 0; e < EMBD; e++) {
        const float wf0 = Wif[(1 + e) * G3 + c];
        const float wf1 = Wif[(1 + e) * G3 + 256 + c];
        const float wf2 = Wif[(1 + e) * G3 + 512 + c];
        const float wb0 = Wib[(1 + e) * G3 + c];
        const float wb1 = Wib[(1 + e) * G3 + 256 + c];
        const float wb2 = Wib[(1 + e) * G3 + 512 + c];
#pragma unroll
        for (int s = 0; s < 8; s++) {
            const float x = emb[s][e];
            af0[s] = fmaf(wf0, x, af0[s]);
            af1[s] = fmaf(wf1, x, af1[s]);
            af2[s] = fmaf(wf2, x, af2[s]);
            ab0[s] = fmaf(wb0, x, ab0[s]);
            ab1[s] = fmaf(wb1, x, ab1[s]);
            ab2[s] = fmaf(wb2, x, ab2[s]);
        }
    }
    const float bf0 = bif[c], bf1 = bif[256 + c], bf2 = bif[512 + c];
    const float bb0 = bib[c], bb1 = bib[256 + c], bb2 = bib[512 + c];
#pragma unroll
    for (int s = 0; s < 8; s++) {
        d_Eg[0][sb + s][c]       = af0[s] + bf0;
        d_Eg[0][sb + s][256 + c] = af1[s] + bf1;
        d_Eg[0][sb + s][512 + c] = af2[s] + bf2;
        d_Eg[1][sb + s][c]       = ab0[s] + bb0;
        d_Eg[1][sb + s][256 + c] = ab1[s] + bb1;
        d_Eg[1][sb + s][512 + c] = ab2[s] + bb2;
    }
}

// =====================================================================
// Kernel B: persistent bidirectional GRU scan.
// grid 128 = 2 dirs x 4 batch-groups(8) x 16 hidden-slices(16 units)
// block 384: thread = (c = tid%48 column-of-slice, ks = tid/48 k-split of 32)
// =====================================================================
__global__ void __launch_bounds__(384, 1) gru_scan_kernel(
    const float* __restrict__ dur, const int* __restrict__ sid,
    const float* __restrict__ Whf, const float* __restrict__ Whb,
    const float* __restrict__ bhnf, const float* __restrict__ bhnb,
    const float* __restrict__ Wif, const float* __restrict__ Wib)
{
    __shared__ __align__(16) float hsm[8 * 256];
    __shared__ float psum[64 * 48];
    __shared__ float ghs[8 * 48];

    const int tid = threadIdx.x;
    const int dir = blockIdx.x >> 6;
    const int bg  = (blockIdx.x >> 4) & 3;
    const int hs  = blockIdx.x & 15;
    const int u0  = hs * 16;

    const float* Wh  = dir ? Whb : Whf;
    const float* bhn = dir ? bhnb : bhnf;
    const float* Wi  = dir ? Wib : Wif;
    const float* Egd = &d_Eg[dir][0][0];
    float* H = &d_H[dir][0][0][0];
    unsigned* cnt = &d_Cnt[dir][bg][0];

    // load my 48-column Wh slice into registers (loop invariant)
    const int c  = tid % 48;
    const int ks = tid / 48;                       // k range [ks*32, ks*32+32)
    const int gcol = (c / 16) * 256 + u0 + (c % 16);
    unsigned long long wp[16];
#pragma unroll
    for (int i = 0; i < 16; i++)
        wp[i] = pk2(Wh[(ks * 32 + 2 * i) * G3 + gcol],
                    Wh[(ks * 32 + 2 * i + 1) * G3 + gcol]);

    // gate-thread constants (tid < 128: b = tid>>4, u = tid&15)
    const int b = tid >> 4;
    const int u = tid & 15;
    const int gb = bg * 8 + b;
    float wi0r = 0.f, wi0z = 0.f, wi0n = 0.f, bhn_u = 0.f;
    int   sid_cur = 0;
    float dur_cur = 0.f;
    if (tid < 128) {
        wi0r  = Wi[u0 + u];
        wi0z  = Wi[256 + u0 + u];
        wi0n  = Wi[512 + u0 + u];
        bhn_u = bhn[u0 + u];
        const int st = dir ? (TT - 1) : 0;
        sid_cur = sid[gb * TT + st];
        dur_cur = dur[gb * TT + st];
        H[(size_t)gb * HH + u0 + u] = 0.f;   // h[0] = 0 for my slice
        __threadfence();
    }
    __syncthreads();
    if (tid == 0)
        asm volatile("red.release.gpu.global.add.u32 [%0], 1;" :: "l"(cnt) : "memory");

    for (int t = 0; t < TT; ++t) {
        // gate-input gathers (independent of recurrence) issued early
        float er = 0.f, ez = 0.f, en = 0.f;
        int sid_nx = 0; float dur_nx = 0.f;
        if (tid < 128) {
            const float* Er = Egd + (size_t)sid_cur * G3;
            er = __ldg(Er + u0 + u);
            ez = __ldg(Er + 256 + u0 + u);
            en = __ldg(Er + 512 + u0 + u);
            if (t + 1 < TT) {
                const int st = dir ? (TT - 2 - t) : (t + 1);
                sid_nx = sid[gb * TT + st];
                dur_nx = dur[gb * TT + st];
            }
        }

        // wait for all 16 slice-CTAs of this (dir, group) to publish h[t]
        if (tid == 0) {
            unsigned v;
            do {
                asm volatile("ld.acquire.gpu.global.u32 %0, [%1];"
                             : "=r"(v) : "l"(cnt + t));
            } while (v < 16u);
        }
        __syncthreads();

        // stage h[t] (8 batches x 256) into smem
        const float* hsrc = H + ((size_t)t * BB + bg * 8) * HH;
        for (int i = tid; i < 2048; i += 384) hsm[i] = __ldcg(hsrc + i);
        __syncthreads();

        // GEMM partial: gh[b][c] over my 32-k slice
        unsigned long long acc[8];
#pragma unroll
        for (int i = 0; i < 8; i++) acc[i] = pk2(0.f, 0.f);
        const float* hbase = hsm + ks * 32;
#pragma unroll
        for (int kk = 0; kk < 32; kk += 4) {
            const unsigned long long w0 = wp[kk >> 1];
            const unsigned long long w1 = wp[(kk >> 1) + 1];
#pragma unroll
            for (int bb2 = 0; bb2 < 8; ++bb2) {
                const ulonglong2 hv =
                    *reinterpret_cast<const ulonglong2*>(hbase + bb2 * 256 + kk);
                fma2(acc[bb2], w0, hv.x);
                fma2(acc[bb2], w1, hv.y);
            }
        }
#pragma unroll
        for (int bb2 = 0; bb2 < 8; ++bb2) {
            const float2 a = up2(acc[bb2]);
            psum[(ks * 8 + bb2) * 48 + c] = a.x + a.y;
        }
        __syncthreads();

        // reduce across k-splits: thread (ks,c) doubles as (b=ks, c)
        {
            float gh = 0.f;
#pragma unroll
            for (int k2 = 0; k2 < 8; k2++) gh += psum[(k2 * 8 + ks) * 48 + c];
            ghs[ks * 48 + c] = gh;
        }
        __syncthreads();

        // gates + state update + publish
        if (tid < 128) {
            const float hr = ghs[b * 48 + u];
            const float hz = ghs[b * 48 + 16 + u];
            const float hn = ghs[b * 48 + 32 + u];
            const float hprev = hsm[b * 256 + u0 + u];
            const float ir  = fmaf(dur_cur, wi0r, er);
            const float iz  = fmaf(dur_cur, wi0z, ez);
            const float inn = fmaf(dur_cur, wi0n, en);
            const float r = 1.f / (1.f + __expf(-(ir + hr)));
            const float z = 1.f / (1.f + __expf(-(iz + hz)));
            const float n = tanhf(fmaf(r, hn + bhn_u, inn));
            const float hnew = (1.f - z) * n + z * hprev;
            H[((size_t)(t + 1) * BB + gb) * HH + u0 + u] = hnew;
            __threadfence();
            sid_cur = sid_nx;
            dur_cur = dur_nx;
        }
        __syncthreads();
        if (tid == 0)
            asm volatile("red.release.gpu.global.add.u32 [%0], 1;"
                         :: "l"(cnt + t + 1) : "memory");
    }
}

// =====================================================================
// Kernel C: out[b,t] = fwd[t+1,b,:].Wd[0:256] + bwd[T-t,b,:].Wd[256:512] + bd
// one warp per (b,t); grid 8192 x 256
// =====================================================================
__global__ void __launch_bounds__(256) out_proj_kernel(
    const float* __restrict__ Wd, const float* __restrict__ bd,
    float* __restrict__ out)
{
    __shared__ float wd[512];
    const int tid = threadIdx.x;
    wd[tid] = Wd[tid];
    wd[tid + 256] = Wd[tid + 256];
    __syncthreads();

    const int warp = tid >> 5, lane = tid & 31;
    const int g = blockIdx.x * 8 + warp;
    const int b = g >> 11;
    const int t = g & 2047;

    const float* hf = &d_H[0][t + 1][b][0];
    const float* hb = &d_H[1][TT - t][b][0];
    float s = 0.f;
#pragma unroll
    for (int i = lane; i < HH; i += 32)
        s = fmaf(hf[i], wd[i], fmaf(hb[i], wd[256 + i], s));
#pragma unroll
    for (int o = 16; o > 0; o >>= 1) s += __shfl_xor_sync(0xffffffffu, s, o);
    if (lane == 0) out[b * TT + t] = s + bd[0];
}

// =====================================================================
extern "C" void kernel_launch(void* const* d_in, const int* in_sizes, int n_in,
                              void* d_out, int out_size)
{
    const float* dur   = (const float*)d_in[0];
    const int*   sid   = (const int*)  d_in[1];
    const float* embed = (const float*)d_in[2];
    const float* Wif   = (const float*)d_in[3];
    const float* Whf   = (const float*)d_in[4];
    const float* bif   = (const float*)d_in[5];
    const float* bhnf  = (const float*)d_in[6];
    const float* Wib   = (const float*)d_in[7];
    const float* Whb   = (const float*)d_in[8];
    const float* bib   = (const float*)d_in[9];
    const float* bhnb  = (const float*)d_in[10];
    const float* Wd    = (const float*)d_in[11];
    const float* bd    = (const float*)d_in[12];
    float* out = (float*)d_out;

    precompute_kernel<<<128, 256>>>(embed, Wif, bif, Wib, bib);
    gru_scan_kernel<<<128, 384>>>(dur, sid, Whf, Whb, bhnf, bhnb, Wif, Wib);
    out_proj_kernel<<<8192, 256>>>(Wd, bd, out);
}